// round 13
// baseline (speedup 1.0000x reference)
#include <cuda_runtime.h>
#include <math.h>
#include <stdint.h>

#define BB 64
#define TT 512
#define EE 256
#define HH 200
#define G4 800          // 4*H
#define CC 20
#define M_ROWS (BB*TT)  // 32768
#define LN_EPS 1e-5f

typedef unsigned long long ull;

// ---------------- scratch (device globals: allocation-free) ----------------
__device__ float g_x[M_ROWS * EE];        // LN'ed embeddings  [B*T, E]
__device__ float g_gxf[M_ROWS * G4];      // gates_x forward   [B*T, 4H]
__device__ float g_gxb[M_ROWS * G4];      // gates_x backward
__device__ float g_feats[M_ROWS * 2 * HH];// [B*T, 400]
__device__ float g_logits[M_ROWS * CC];   // [B*T, 20]
__device__ float g_lossb[BB];

__device__ __forceinline__ float sigf(float x) { return 1.f / (1.f + expf(-x)); }

// ---- packed fp32x2 helpers (FFMA2: 2x fp32 FMA throughput on sm_103a) ----
__device__ __forceinline__ ull pack2(float x) {
    ull r;
    asm("mov.b64 %0, {%1, %1};" : "=l"(r) : "f"(x));
    return r;
}
__device__ __forceinline__ void fma2(ull& d, ull a, ull b) {
    asm("fma.rn.f32x2 %0, %1, %2, %0;" : "+l"(d) : "l"(a), "l"(b));
}
__device__ __forceinline__ float2 unpack2(ull v) {
    float2 f;
    asm("mov.b64 {%0, %1}, %2;" : "=f"(f.x), "=f"(f.y) : "l"(v));
    return f;
}

__device__ __forceinline__ uint32_t smem_u32(const void* p) {
    uint32_t a;
    asm("{ .reg .u64 t; cvta.to.shared.u64 t, %1; cvt.u32.u64 %0, t; }" : "=r"(a) : "l"(p));
    return a;
}
__device__ __forceinline__ uint32_t mapa_rank(uint32_t local_addr, uint32_t rank) {
    uint32_t rem;
    asm("mapa.shared::cluster.u32 %0, %1, %2;" : "=r"(rem) : "r"(local_addr), "r"(rank));
    return rem;
}
__device__ __forceinline__ void st_cluster_f32(uint32_t addr, float v) {
    asm volatile("st.shared::cluster.f32 [%0], %1;" :: "r"(addr), "f"(v) : "memory");
}
__device__ __forceinline__ void cluster_bar() {
    asm volatile("barrier.cluster.arrive.aligned;" ::: "memory");
    asm volatile("barrier.cluster.wait.aligned;" ::: "memory");
}

// ---------------- 1. embedding + layernorm ----------------
__global__ void embed_ln_kernel(const int* __restrict__ words,
                                const float* __restrict__ table,
                                const float* __restrict__ gamma,
                                const float* __restrict__ beta) {
    int row = blockIdx.x;
    int tid = threadIdx.x;           // 256 = E
    int w = words[row];
    float v = table[(size_t)w * EE + tid];

    __shared__ float red[8];
    float s = v;
    #pragma unroll
    for (int o = 16; o; o >>= 1) s += __shfl_xor_sync(~0u, s, o);
    if ((tid & 31) == 0) red[tid >> 5] = s;
    __syncthreads();
    float tot = 0.f;
    #pragma unroll
    for (int i = 0; i < 8; i++) tot += red[i];
    float mu = tot * (1.f / EE);
    __syncthreads();
    float d = v - mu;
    float s2 = d * d;
    #pragma unroll
    for (int o = 16; o; o >>= 1) s2 += __shfl_xor_sync(~0u, s2, o);
    if ((tid & 31) == 0) red[tid >> 5] = s2;
    __syncthreads();
    float tot2 = 0.f;
    #pragma unroll
    for (int i = 0; i < 8; i++) tot2 += red[i];
    float var = tot2 * (1.f / EE);

    g_x[(size_t)row * EE + tid] = d * rsqrtf(var + LN_EPS) * gamma[tid] + beta[tid];
}

// ---------------- 2. gates_x GEMM: both dirs fused, 128x64 tile, f32x2 ----------------
__global__ void __launch_bounds__(256) gemm_gates_kernel(
                                  const float* __restrict__ Wf,
                                  const float* __restrict__ biasf,
                                  const float* __restrict__ Wb,
                                  const float* __restrict__ biasb) {
    int dir = blockIdx.z;
    float* G = dir ? g_gxb : g_gxf;
    const float* W = dir ? Wb : Wf;
    const float* bias = dir ? biasb : biasf;
    __shared__ __align__(16) float As[16][132];   // [kk][row 0..127]
    __shared__ __align__(16) float Bs[16][68];    // [kk][n 0..63]
    int tid = threadIdx.x;           // 256
    int tx = tid & 15, ty = tid >> 4;
    int m0 = blockIdx.y * 128, n0 = blockIdx.x * 64;

    ull acc2[4][4];
    #pragma unroll
    for (int p = 0; p < 4; p++)
        #pragma unroll
        for (int j = 0; j < 4; j++) acc2[p][j] = 0ull;

    for (int k0 = 0; k0 < EE; k0 += 16) {
        #pragma unroll
        for (int q = 0; q < 2; q++) {
            int f4 = tid * 2 + q;
            int row = f4 >> 2, kq = f4 & 3;
            float4 v = *(const float4*)&g_x[(size_t)(m0 + row) * EE + k0 + kq * 4];
            As[kq * 4 + 0][row] = v.x; As[kq * 4 + 1][row] = v.y;
            As[kq * 4 + 2][row] = v.z; As[kq * 4 + 3][row] = v.w;
        }
        {
            int row = tid >> 2, kq = tid & 3;
            int n = n0 + row;
            float4 v = (n < G4) ? *(const float4*)&W[(size_t)n * EE + k0 + kq * 4]
                                : make_float4(0.f, 0.f, 0.f, 0.f);
            Bs[kq * 4 + 0][row] = v.x; Bs[kq * 4 + 1][row] = v.y;
            Bs[kq * 4 + 2][row] = v.z; Bs[kq * 4 + 3][row] = v.w;
        }
        __syncthreads();
        #pragma unroll
        for (int kk = 0; kk < 16; kk++) {
            ulonglong2 avA = *(const ulonglong2*)&As[kk][ty * 8];
            ulonglong2 avB = *(const ulonglong2*)&As[kk][ty * 8 + 4];
            float4 b4 = *(const float4*)&Bs[kk][tx * 4];
            ull ap[4] = {avA.x, avA.y, avB.x, avB.y};
            ull bd[4] = {pack2(b4.x), pack2(b4.y), pack2(b4.z), pack2(b4.w)};
            #pragma unroll
            for (int p = 0; p < 4; p++)
                #pragma unroll
                for (int j = 0; j < 4; j++) fma2(acc2[p][j], ap[p], bd[j]);
        }
        __syncthreads();
    }

    int nb = n0 + tx * 4;
    if (nb < G4) {
        float b0 = bias[nb], b1 = bias[nb + 1], b2 = bias[nb + 2], b3 = bias[nb + 3];
        #pragma unroll
        for (int p = 0; p < 4; p++) {
            float2 f0 = unpack2(acc2[p][0]);
            float2 f1 = unpack2(acc2[p][1]);
            float2 f2 = unpack2(acc2[p][2]);
            float2 f3 = unpack2(acc2[p][3]);
            int m = m0 + ty * 8 + p * 2;
            *(float4*)&G[(size_t)m * G4 + nb] =
                make_float4(f0.x + b0, f1.x + b1, f2.x + b2, f3.x + b3);
            *(float4*)&G[(size_t)(m + 1) * G4 + nb] =
                make_float4(f0.y + b0, f1.y + b1, f2.y + b2, f3.y + b3);
        }
    }
}

// ---------------- 3. BiLSTM recurrence: 4-CTA clusters, 8 batches, row-major w ----------------
#define NRANK 4
#define NB 8
#define SLICE 50
#define LROWS 200
#define KPAD 204                       // padded k stride (bank-conflict-free)
#define WS_ELEMS (LROWS * KPAD)        // 40800
#define HB_ELEMS (NB * KPAD)           // 1632 per parity
#define GP_ELEMS (2 * LROWS * NB)      // 3200 (two k-half partials)
#define LSTM_SMEM_FLOATS (WS_ELEMS + 2 * HB_ELEMS + GP_ELEMS)  // 47264 -> 189,056 B

__global__ void __cluster_dims__(NRANK, 1, 1) __launch_bounds__(512, 1)
lstm_cluster_kernel(const int* __restrict__ seq_len,
                    const float* __restrict__ w_hh_f,
                    const float* __restrict__ w_hh_b) {
    extern __shared__ __align__(16) float smem[];
    float* ws2   = smem;                    // [r=200][KPAD] row-major (native w_hh layout)
    float* hbuf  = smem + WS_ELEMS;         // [2][b=8][KPAD]  h, k-contiguous per batch
    float* gpart = hbuf + 2 * HB_ELEMS;     // [half][lr=200][b=8]

    int tid = threadIdx.x;                  // 512
    uint32_t cid  = blockIdx.x >> 2;        // 0..15
    uint32_t rank = blockIdx.x & 3;
    int dir  = (int)(cid >> 3);
    int bgrp = (int)(cid & 7);              // batches bgrp*8 .. +7

    const float* gx = dir ? g_gxb : g_gxf;
    const float* w  = dir ? w_hh_b : w_hh_f;

    // stage weight slice directly from w_hh (row-major [grow][k]) -> ws2[r][k]
    for (int idx = tid; idx < LROWS * HH; idx += 512) {
        int rr = idx / HH, k = idx - rr * HH;
        int gr = (rr / SLICE) * HH + (int)rank * SLICE + (rr % SLICE);
        ws2[rr * KPAD + k] = w[(size_t)gr * HH + k];
    }
    for (int i = tid; i < 2 * HB_ELEMS + GP_ELEMS; i += 512) hbuf[i] = 0.f;

    int maxlen = 0;
    #pragma unroll
    for (int b = 0; b < NB; b++) maxlen = max(maxlen, seq_len[bgrp * NB + b]);

    // gemv role: r = tid&255 (active r<200), half = tid>>8 (k in [half*100, +100))
    int r    = tid & 255;
    int half = tid >> 8;

    // epilogue role: tid = jl*8 + bl  (tid < 400)
    int bl = tid & 7;
    int jl = tid >> 3;
    int bglob = bgrp * NB + bl;
    int len = (tid < 400) ? seq_len[bglob] : 0;
    int jg = (int)rank * SLICE + jl;
    const float* gxrow = gx + (size_t)bglob * TT * G4 + jg;   // + t*G4 + g*HH
    float c_reg = 0.f, h_reg = 0.f;

    // hoisted remote hbuf base addresses
    uint32_t hb_local = smem_u32(hbuf);
    uint32_t rem0 = mapa_rank(hb_local, 0);
    uint32_t rem1 = mapa_rank(hb_local, 1);
    uint32_t rem2 = mapa_rank(hb_local, 2);
    uint32_t rem3 = mapa_rank(hb_local, 3);
    uint32_t my_off = (uint32_t)(bl * KPAD + jg) * 4;         // within a parity buffer

    __syncthreads();
    cluster_bar();

    int p = 0;
    for (int s = 0; s < maxlen; s++) {
        int t = dir ? (maxlen - 1 - s) : s;

        // prefetch gates_x for the epilogue (hidden under gemv)
        float gxv0, gxv1, gxv2, gxv3;
        if (tid < 400) {
            const float* gb = gxrow + (size_t)t * G4;
            gxv0 = gb[0];
            gxv1 = gb[HH];
            gxv2 = gb[2 * HH];
            gxv3 = gb[3 * HH];
        }

        // gemv: acc_b (packed: lo=even k, hi=odd k)
        if (r < LROWS) {
            const float* wp = ws2 + r * KPAD + half * 100;
            const float* hp = hbuf + p * HB_ELEMS + half * 100;
            ull a0 = 0, a1 = 0, a2 = 0, a3 = 0, a4 = 0, a5 = 0, a6 = 0, a7 = 0;
            #pragma unroll 5
            for (int kk = 0; kk < 100; kk += 4) {
                ulonglong2 w2 = *(const ulonglong2*)(wp + kk);
                ulonglong2 h0 = *(const ulonglong2*)(hp + 0 * KPAD + kk);
                ulonglong2 h1 = *(const ulonglong2*)(hp + 1 * KPAD + kk);
                ulonglong2 h2 = *(const ulonglong2*)(hp + 2 * KPAD + kk);
                ulonglong2 h3 = *(const ulonglong2*)(hp + 3 * KPAD + kk);
                ulonglong2 h4 = *(const ulonglong2*)(hp + 4 * KPAD + kk);
                ulonglong2 h5 = *(const ulonglong2*)(hp + 5 * KPAD + kk);
                ulonglong2 h6 = *(const ulonglong2*)(hp + 6 * KPAD + kk);
                ulonglong2 h7 = *(const ulonglong2*)(hp + 7 * KPAD + kk);
                fma2(a0, w2.x, h0.x); fma2(a0, w2.y, h0.y);
                fma2(a1, w2.x, h1.x); fma2(a1, w2.y, h1.y);
                fma2(a2, w2.x, h2.x); fma2(a2, w2.y, h2.y);
                fma2(a3, w2.x, h3.x); fma2(a3, w2.y, h3.y);
                fma2(a4, w2.x, h4.x); fma2(a4, w2.y, h4.y);
                fma2(a5, w2.x, h5.x); fma2(a5, w2.y, h5.y);
                fma2(a6, w2.x, h6.x); fma2(a6, w2.y, h6.y);
                fma2(a7, w2.x, h7.x); fma2(a7, w2.y, h7.y);
            }
            // horizontal add (even+odd k) and store partials
            float2 f0 = unpack2(a0), f1 = unpack2(a1), f2 = unpack2(a2), f3 = unpack2(a3);
            float2 f4 = unpack2(a4), f5 = unpack2(a5), f6 = unpack2(a6), f7 = unpack2(a7);
            float* gp = gpart + half * (LROWS * NB) + r * NB;
            *(float4*)gp       = make_float4(f0.x + f0.y, f1.x + f1.y, f2.x + f2.y, f3.x + f3.y);
            *(float4*)(gp + 4) = make_float4(f4.x + f4.y, f5.x + f5.y, f6.x + f6.y, f7.x + f7.y);
        }
        __syncthreads();

        if (tid < 400) {
            const float* g0 = gpart;
            const float* g1 = gpart + LROWS * NB;
            int i0 = (0 * SLICE + jl) * NB + bl;
            int i1 = (1 * SLICE + jl) * NB + bl;
            int i2 = (2 * SLICE + jl) * NB + bl;
            int i3 = (3 * SLICE + jl) * NB + bl;
            float gi = g0[i0] + g1[i0] + gxv0;
            float gf = g0[i1] + g1[i1] + gxv1;
            float gg = g0[i2] + g1[i2] + gxv2;
            float go = g0[i3] + g1[i3] + gxv3;
            float cn = fmaf(sigf(gf), c_reg, sigf(gi) * tanhf(gg));
            float hn = sigf(go) * tanhf(cn);
            if (t < len) { c_reg = cn; h_reg = hn; }
            uint32_t off = (uint32_t)(1 - p) * (HB_ELEMS * 4) + my_off;
            st_cluster_f32(rem0 + off, h_reg);
            st_cluster_f32(rem1 + off, h_reg);
            st_cluster_f32(rem2 + off, h_reg);
            st_cluster_f32(rem3 + off, h_reg);
            g_feats[((size_t)bglob * TT + t) * (2 * HH) + dir * HH + jg] = h_reg;
        }
        cluster_bar();
        p ^= 1;
    }

    // tail t in [maxlen, TT): fwd -> frozen h, bwd -> zeros
    if (tid < 400) {
        float tv = dir ? 0.f : h_reg;
        for (int t = maxlen; t < TT; t++)
            g_feats[((size_t)bglob * TT + t) * (2 * HH) + dir * HH + jg] = tv;
    }
}

// ---------------- 4. fc + log_softmax (warp per token) ----------------
__global__ void logits_kernel(const float* __restrict__ fcw,
                              const float* __restrict__ fcb) {
    int warp = (blockIdx.x * blockDim.x + threadIdx.x) >> 5;
    int lane = threadIdx.x & 31;
    if (warp >= M_ROWS) return;
    const float4* f4 = (const float4*)(g_feats + (size_t)warp * 400);
    float acc;
    if (lane < CC) {
        const float4* w4 = (const float4*)(fcw + (size_t)lane * 400);
        float a = 0.f;
        #pragma unroll 4
        for (int k = 0; k < 100; k++) {
            float4 f = f4[k], w = w4[k];
            a = fmaf(f.x, w.x, a); a = fmaf(f.y, w.y, a);
            a = fmaf(f.z, w.z, a); a = fmaf(f.w, w.w, a);
        }
        acc = a + fcb[lane];
    } else {
        acc = -INFINITY;
    }
    float m = acc;
    #pragma unroll
    for (int o = 16; o; o >>= 1) m = fmaxf(m, __shfl_xor_sync(~0u, m, o));
    float e = (lane < CC) ? expf(acc - m) : 0.f;
    float ss = e;
    #pragma unroll
    for (int o = 16; o; o >>= 1) ss += __shfl_xor_sync(~0u, ss, o);
    float lse = m + logf(ss);
    if (lane < CC) g_logits[(size_t)warp * CC + lane] = acc - lse;
}

// ---------------- 5. CRF NLL per batch (one warp per sample) ----------------
__global__ void crf_kernel(const int* __restrict__ target,
                           const int* __restrict__ seq_len,
                           const float* __restrict__ trans,
                           const float* __restrict__ start_s,
                           const float* __restrict__ end_s) {
    int b = blockIdx.x;
    int lane = threadIdx.x;          // 32
    __shared__ float s_trans[CC * CC];
    __shared__ float s_alpha[CC];
    for (int i = lane; i < CC * CC; i += 32) s_trans[i] = trans[i];
    int len = seq_len[b];
    const float* lg = g_logits + (size_t)b * TT * CC;
    const int* tg = target + (size_t)b * TT;
    if (lane < CC) s_alpha[lane] = start_s[lane] + lg[lane];
    __syncthreads();

    for (int t = 1; t < TT; t++) {
        if (t >= len) break;
        float newa = 0.f;
        if (lane < CC) {
            float m = -INFINITY;
            #pragma unroll
            for (int i = 0; i < CC; i++)
                m = fmaxf(m, s_alpha[i] + s_trans[i * CC + lane]);
            float s = 0.f;
            #pragma unroll
            for (int i = 0; i < CC; i++)
                s += expf(s_alpha[i] + s_trans[i * CC + lane] - m);
            newa = m + logf(s) + lg[t * CC + lane];
        }
        __syncthreads();
        if (lane < CC) s_alpha[lane] = newa;
        __syncthreads();
    }

    float v = (lane < CC) ? s_alpha[lane] + end_s[lane] : -INFINITY;
    float m = v;
    #pragma unroll
    for (int o = 16; o; o >>= 1) m = fmaxf(m, __shfl_xor_sync(~0u, m, o));
    float e = (lane < CC) ? expf(v - m) : 0.f;
    float ss = e;
    #pragma unroll
    for (int o = 16; o; o >>= 1) ss += __shfl_xor_sync(~0u, ss, o);
    float logZ = m + logf(ss);

    float es = 0.f;
    for (int t = lane; t < len; t += 32) es += lg[t * CC + tg[t]];
    float ts = 0.f;
    for (int t = 1 + lane; t < len; t += 32) ts += s_trans[tg[t - 1] * CC + tg[t]];
    float g = es + ts;
    #pragma unroll
    for (int o = 16; o; o >>= 1) g += __shfl_xor_sync(~0u, g, o);
    if (lane == 0) {
        float gold = g + start_s[tg[0]] + end_s[tg[len - 1]];
        g_lossb[b] = logZ - gold;
    }
}

// ---------------- 6. mean reduce ----------------
__global__ void reduce_loss_kernel(float* out) {
    int lane = threadIdx.x;          // 32
    float s = g_lossb[lane] + g_lossb[lane + 32];
    #pragma unroll
    for (int o = 16; o; o >>= 1) s += __shfl_xor_sync(~0u, s, o);
    if (lane == 0) out[0] = s * (1.f / BB);
}

// ---------------- launch ----------------
extern "C" void kernel_launch(void* const* d_in, const int* in_sizes, int n_in,
                              void* d_out, int out_size) {
    const int*   words   = (const int*)  d_in[0];
    const int*   seq_len = (const int*)  d_in[1];
    const int*   target  = (const int*)  d_in[2];
    const float* table   = (const float*)d_in[3];
    const float* gamma   = (const float*)d_in[4];
    const float* beta    = (const float*)d_in[5];
    const float* w_ih_f  = (const float*)d_in[6];
    const float* w_hh_f  = (const float*)d_in[7];
    const float* b_f     = (const float*)d_in[8];
    const float* w_ih_b  = (const float*)d_in[9];
    const float* w_hh_b  = (const float*)d_in[10];
    const float* b_b     = (const float*)d_in[11];
    const float* fc_w    = (const float*)d_in[12];
    const float* fc_b    = (const float*)d_in[13];
    const float* trans   = (const float*)d_in[14];
    const float* start_s = (const float*)d_in[15];
    const float* end_s   = (const float*)d_in[16];
    float* out = (float*)d_out;

    static const int lstm_smem = LSTM_SMEM_FLOATS * (int)sizeof(float);  // 189,056 B
    cudaFuncSetAttribute(lstm_cluster_kernel,
                         cudaFuncAttributeMaxDynamicSharedMemorySize, lstm_smem);

    embed_ln_kernel<<<M_ROWS, 256>>>(words, table, gamma, beta);

    dim3 ggrid((G4 + 63) / 64, M_ROWS / 128, 2);
    gemm_gates_kernel<<<ggrid, 256>>>(w_ih_f, b_f, w_ih_b, b_b);

    lstm_cluster_kernel<<<16 * NRANK, 512, lstm_smem>>>(seq_len, w_hh_f, w_hh_b);

    logits_kernel<<<M_ROWS / 8, 256>>>(fc_w, fc_b);

    crf_kernel<<<BB, 32>>>(target, seq_len, trans, start_s, end_s);
    reduce_loss_kernel<<<1, 32>>>(out);
}

// round 17
// speedup vs baseline: 1.6919x; 1.6919x over previous
#include <cuda_runtime.h>
#include <cuda_bf16.h>
#include <math.h>
#include <stdint.h>

#define BB 64
#define TT 512
#define EE 256
#define HH 200
#define G4 800          // 4*H
#define CC 20
#define M_ROWS (BB*TT)  // 32768
#define LN_EPS 1e-5f

typedef unsigned long long ull;

// single dynamic-smem symbol (consistent type across kernels)
extern __shared__ __align__(16) char dynsmem[];

// ---------------- scratch (device globals: allocation-free) ----------------
__device__ float g_x[M_ROWS * EE];        // LN'ed embeddings  [B*T, E]
__device__ float g_gxf[M_ROWS * G4];      // gates_x forward   [B*T, 4H]
__device__ float g_gxb[M_ROWS * G4];      // gates_x backward
__device__ float g_feats[M_ROWS * 2 * HH];// [B*T, 400]
__device__ float g_logits[M_ROWS * CC];   // [B*T, 20]
__device__ float g_lossb[BB];

__device__ __forceinline__ float sigf(float x) { return 1.f / (1.f + expf(-x)); }
__device__ __forceinline__ float fast_sig(float x) { return 1.f / (1.f + __expf(-x)); }
__device__ __forceinline__ float fast_tanh(float x) { return 2.f / (1.f + __expf(-2.f * x)) - 1.f; }

// ---- packed fp32x2 helpers (FFMA2) ----
__device__ __forceinline__ ull pack2(float x) {
    ull r; asm("mov.b64 %0, {%1, %1};" : "=l"(r) : "f"(x)); return r;
}
__device__ __forceinline__ void fma2(ull& d, ull a, ull b) {
    asm("fma.rn.f32x2 %0, %1, %2, %0;" : "+l"(d) : "l"(a), "l"(b));
}
__device__ __forceinline__ float2 unpack2(ull v) {
    float2 f; asm("mov.b64 {%0, %1}, %2;" : "=f"(f.x), "=f"(f.y) : "l"(v)); return f;
}

// ---- smem / cluster helpers ----
__device__ __forceinline__ uint32_t smem_u32(const void* p) {
    uint32_t a;
    asm("{ .reg .u64 t; cvta.to.shared.u64 t, %1; cvt.u32.u64 %0, t; }" : "=r"(a) : "l"(p));
    return a;
}
__device__ __forceinline__ uint32_t mapa_rank(uint32_t local_addr, uint32_t rank) {
    uint32_t rem;
    asm("mapa.shared::cluster.u32 %0, %1, %2;" : "=r"(rem) : "r"(local_addr), "r"(rank));
    return rem;
}
__device__ __forceinline__ void st_cluster_b16(uint32_t addr, uint16_t v) {
    asm volatile("st.shared::cluster.b16 [%0], %1;" :: "r"(addr), "h"(v) : "memory");
}
__device__ __forceinline__ void cluster_bar() {
    asm volatile("barrier.cluster.arrive.aligned;" ::: "memory");
    asm volatile("barrier.cluster.wait.aligned;" ::: "memory");
}

// ---- mma.sync helpers (HMMA path, valid on base sm_103 target) ----
__device__ __forceinline__ void ldmatrix_x4(uint32_t& r0, uint32_t& r1, uint32_t& r2, uint32_t& r3,
                                            uint32_t addr) {
    asm volatile("ldmatrix.sync.aligned.m8n8.x4.shared.b16 {%0,%1,%2,%3}, [%4];"
                 : "=r"(r0), "=r"(r1), "=r"(r2), "=r"(r3) : "r"(addr));
}
__device__ __forceinline__ void ldmatrix_x2(uint32_t& r0, uint32_t& r1, uint32_t addr) {
    asm volatile("ldmatrix.sync.aligned.m8n8.x2.shared.b16 {%0,%1}, [%2];"
                 : "=r"(r0), "=r"(r1) : "r"(addr));
}
__device__ __forceinline__ void mma_bf16(float& c0, float& c1, float& c2, float& c3,
                                         uint32_t a0, uint32_t a1, uint32_t a2, uint32_t a3,
                                         uint32_t b0, uint32_t b1) {
    asm volatile("mma.sync.aligned.m16n8k16.row.col.f32.bf16.bf16.f32 "
                 "{%0,%1,%2,%3}, {%4,%5,%6,%7}, {%8,%9}, {%0,%1,%2,%3};"
                 : "+f"(c0), "+f"(c1), "+f"(c2), "+f"(c3)
                 : "r"(a0), "r"(a1), "r"(a2), "r"(a3), "r"(b0), "r"(b1));
}

// ---------------- 1. embedding + layernorm ----------------
__global__ void embed_ln_kernel(const int* __restrict__ words,
                                const float* __restrict__ table,
                                const float* __restrict__ gamma,
                                const float* __restrict__ beta) {
    int row = blockIdx.x;
    int tid = threadIdx.x;           // 256 = E
    int w = words[row];
    float v = table[(size_t)w * EE + tid];

    __shared__ float red[8];
    float s = v;
    #pragma unroll
    for (int o = 16; o; o >>= 1) s += __shfl_xor_sync(~0u, s, o);
    if ((tid & 31) == 0) red[tid >> 5] = s;
    __syncthreads();
    float tot = 0.f;
    #pragma unroll
    for (int i = 0; i < 8; i++) tot += red[i];
    float mu = tot * (1.f / EE);
    __syncthreads();
    float d = v - mu;
    float s2 = d * d;
    #pragma unroll
    for (int o = 16; o; o >>= 1) s2 += __shfl_xor_sync(~0u, s2, o);
    if ((tid & 31) == 0) red[tid >> 5] = s2;
    __syncthreads();
    float tot2 = 0.f;
    #pragma unroll
    for (int i = 0; i < 8; i++) tot2 += red[i];
    float var = tot2 * (1.f / EE);

    g_x[(size_t)row * EE + tid] = d * rsqrtf(var + LN_EPS) * gamma[tid] + beta[tid];
}

// ---------------- 2. gates_x GEMM: both dirs fused, 128x64 tile, f32x2 ----------------
__global__ void __launch_bounds__(256) gemm_gates_kernel(
                                  const float* __restrict__ Wf,
                                  const float* __restrict__ biasf,
                                  const float* __restrict__ Wb,
                                  const float* __restrict__ biasb) {
    int dir = blockIdx.z;
    float* G = dir ? g_gxb : g_gxf;
    const float* W = dir ? Wb : Wf;
    const float* bias = dir ? biasb : biasf;
    float* sm = (float*)dynsmem;
    float (*As)[132] = (float(*)[132])sm;              // [16][132]
    float (*Bs)[68]  = (float(*)[68])(sm + 16 * 132);  // [16][68]
    int tid = threadIdx.x;           // 256
    int tx = tid & 15, ty = tid >> 4;
    int m0 = blockIdx.y * 128, n0 = blockIdx.x * 64;

    ull acc2[4][4];
    #pragma unroll
    for (int p = 0; p < 4; p++)
        #pragma unroll
        for (int j = 0; j < 4; j++) acc2[p][j] = 0ull;

    for (int k0 = 0; k0 < EE; k0 += 16) {
        #pragma unroll
        for (int q = 0; q < 2; q++) {
            int f4 = tid * 2 + q;
            int row = f4 >> 2, kq = f4 & 3;
            float4 v = *(const float4*)&g_x[(size_t)(m0 + row) * EE + k0 + kq * 4];
            As[kq * 4 + 0][row] = v.x; As[kq * 4 + 1][row] = v.y;
            As[kq * 4 + 2][row] = v.z; As[kq * 4 + 3][row] = v.w;
        }
        {
            int row = tid >> 2, kq = tid & 3;
            int n = n0 + row;
            float4 v = (n < G4) ? *(const float4*)&W[(size_t)n * EE + k0 + kq * 4]
                                : make_float4(0.f, 0.f, 0.f, 0.f);
            Bs[kq * 4 + 0][row] = v.x; Bs[kq * 4 + 1][row] = v.y;
            Bs[kq * 4 + 2][row] = v.z; Bs[kq * 4 + 3][row] = v.w;
        }
        __syncthreads();
        #pragma unroll
        for (int kk = 0; kk < 16; kk++) {
            ulonglong2 avA = *(const ulonglong2*)&As[kk][ty * 8];
            ulonglong2 avB = *(const ulonglong2*)&As[kk][ty * 8 + 4];
            float4 b4 = *(const float4*)&Bs[kk][tx * 4];
            ull ap[4] = {avA.x, avA.y, avB.x, avB.y};
            ull bd[4] = {pack2(b4.x), pack2(b4.y), pack2(b4.z), pack2(b4.w)};
            #pragma unroll
            for (int p = 0; p < 4; p++)
                #pragma unroll
                for (int j = 0; j < 4; j++) fma2(acc2[p][j], ap[p], bd[j]);
        }
        __syncthreads();
    }

    int nb = n0 + tx * 4;
    if (nb < G4) {
        float b0 = bias[nb], b1 = bias[nb + 1], b2 = bias[nb + 2], b3 = bias[nb + 3];
        #pragma unroll
        for (int p = 0; p < 4; p++) {
            float2 f0 = unpack2(acc2[p][0]);
            float2 f1 = unpack2(acc2[p][1]);
            float2 f2 = unpack2(acc2[p][2]);
            float2 f3 = unpack2(acc2[p][3]);
            int m = m0 + ty * 8 + p * 2;
            *(float4*)&G[(size_t)m * G4 + nb] =
                make_float4(f0.x + b0, f1.x + b1, f2.x + b2, f3.x + b3);
            *(float4*)&G[(size_t)(m + 1) * G4 + nb] =
                make_float4(f0.y + b0, f1.y + b1, f2.y + b2, f3.y + b3);
        }
    }
}
#define GEMM_SMEM ((16 * 132 + 16 * 68) * 4)

// ---------------- 3. BiLSTM recurrence: mma.sync, weights in registers ----------------
// Cluster of 4 CTAs = one (dir, 8-batch) group. CTA rank owns 200 gate rows
// (50 per gate). Per step each CTA computes a 200x8x200 GEMM on HMMA:
// 13 warps x m16 tiles, K=200 (pad 208), N=8 batches. Weight A-fragments are
// register-resident for the whole kernel. h circulates as bf16 via DSMEM.
#define NRANK 4
#define NB 8
#define SLICE 50
#define LROWS 200
#define MPAD 208
#define KPADE 232                    // bf16 elems per row; 464B stride -> ldmatrix conflict-free
#define WS_OFF 0
#define WS_BYTES (MPAD * KPADE * 2)              // 96512
#define HB_OFF WS_BYTES
#define HB_BYTES (2 * NB * KPADE * 2)            // 7424
#define GB_OFF (HB_OFF + HB_BYTES)               // 103936
#define GB_BYTES (MPAD * NB * 4)                 // 6656
#define LSTM_SMEM (GB_OFF + GB_BYTES)            // 110592

__global__ void __cluster_dims__(NRANK, 1, 1) __launch_bounds__(512, 1)
lstm_cluster_kernel(const int* __restrict__ seq_len,
                    const float* __restrict__ w_hh_f,
                    const float* __restrict__ w_hh_b) {
    char* smem = dynsmem;
    uint32_t smem_base = smem_u32(smem);
    __nv_bfloat16* ws_h = (__nv_bfloat16*)(smem + WS_OFF);   // [208][232]
    float* gbuf = (float*)(smem + GB_OFF);                    // [208][8]

    int tid = threadIdx.x;                      // 512
    int wid = tid >> 5, lane = tid & 31;
    uint32_t cid  = blockIdx.x >> 2;            // 0..15
    uint32_t rank = blockIdx.x & 3;
    int dir  = (int)(cid >> 3);
    int bgrp = (int)(cid & 7);

    const float* gx = dir ? g_gxb : g_gxf;
    const float* w  = dir ? w_hh_b : w_hh_f;

    // zero ws + hbuf + gbuf
    for (int i = tid; i < LSTM_SMEM / 4; i += 512) ((uint32_t*)smem)[i] = 0u;
    __syncthreads();
    // stage weights: ws_h[m][k] = bf16(w[grow(m)][k])
    for (int idx = tid; idx < LROWS * HH; idx += 512) {
        int m = idx / HH, k = idx - m * HH;
        int gr = (m / SLICE) * HH + (int)rank * SLICE + (m % SLICE);
        ws_h[m * KPADE + k] = __float2bfloat16(w[(size_t)gr * HH + k]);
    }

    int maxlen = 0;
    #pragma unroll
    for (int b = 0; b < NB; b++) maxlen = max(maxlen, seq_len[bgrp * NB + b]);
    __syncthreads();

    // --- preload A fragments (weights): 13 k-iters x 4 regs ---
    uint32_t wf[13][4];
    int m0 = wid * 16;
    if (wid < 13) {
        int arow = m0 + (lane & 15);
        int acol = (lane >> 4) * 8;
        uint32_t a_addr = smem_base + WS_OFF + (uint32_t)(arow * KPADE + acol) * 2;
        #pragma unroll
        for (int kk = 0; kk < 13; kk++)
            ldmatrix_x4(wf[kk][0], wf[kk][1], wf[kk][2], wf[kk][3], a_addr + kk * 32);
    }

    // --- B (h) ldmatrix address: hbuf[p][brow][bcolhalf + kk*16] ---
    int lb = lane & 15;
    int brow = lb & 7;
    int bcol = (lb >> 3) * 8;
    uint32_t b_addr[2];
    #pragma unroll
    for (int p = 0; p < 2; p++)
        b_addr[p] = smem_base + HB_OFF + (uint32_t)((p * NB + brow) * KPADE + bcol) * 2;

    // --- epilogue role: tid = jl*8 + bl (tid < 400) ---
    int bl = tid & 7;
    int jl = tid >> 3;
    int bglob = bgrp * NB + bl;
    int len = (tid < 400) ? seq_len[bglob] : 0;
    int jg = (int)rank * SLICE + jl;
    const float* gxrow = gx + (size_t)bglob * TT * G4 + jg;
    float c_reg = 0.f, h_reg = 0.f;

    // remote hbuf base addresses (hoisted mapa)
    uint32_t hb_local = smem_base + HB_OFF;
    uint32_t rem0 = mapa_rank(hb_local, 0);
    uint32_t rem1 = mapa_rank(hb_local, 1);
    uint32_t rem2 = mapa_rank(hb_local, 2);
    uint32_t rem3 = mapa_rank(hb_local, 3);

    cluster_bar();

    int p = 0;
    for (int s = 0; s < maxlen; s++) {
        int t = dir ? (maxlen - 1 - s) : s;

        // prefetch gx for the epilogue (overlaps the mma phase)
        float gxv0, gxv1, gxv2, gxv3;
        if (tid < 400) {
            const float* gb = gxrow + (size_t)t * G4;
            gxv0 = gb[0];
            gxv1 = gb[HH];
            gxv2 = gb[2 * HH];
            gxv3 = gb[3 * HH];
        }

        // mma phase: C[m][n] = sum_k ws[m][k] * h[n][k]
        if (wid < 13) {
            float c0 = 0.f, c1 = 0.f, c2 = 0.f, c3 = 0.f;
            uint32_t ba = b_addr[p];
            #pragma unroll
            for (int kk = 0; kk < 13; kk++) {
                uint32_t b0, b1;
                ldmatrix_x2(b0, b1, ba + kk * 32);
                mma_bf16(c0, c1, c2, c3, wf[kk][0], wf[kk][1], wf[kk][2], wf[kk][3], b0, b1);
            }
            int gid = lane >> 2, tig = lane & 3;
            float* g0 = gbuf + (m0 + gid) * NB + tig * 2;
            *(float2*)g0 = make_float2(c0, c1);
            *(float2*)(g0 + 8 * NB) = make_float2(c2, c3);
        }
        __syncthreads();

        if (tid < 400) {
            float gi = gbuf[(0 * SLICE + jl) * NB + bl] + gxv0;
            float gf = gbuf[(1 * SLICE + jl) * NB + bl] + gxv1;
            float gg = gbuf[(2 * SLICE + jl) * NB + bl] + gxv2;
            float go = gbuf[(3 * SLICE + jl) * NB + bl] + gxv3;
            float cn = fmaf(fast_sig(gf), c_reg, fast_sig(gi) * fast_tanh(gg));
            float hn = fast_sig(go) * fast_tanh(cn);
            if (t < len) { c_reg = cn; h_reg = hn; }
            __nv_bfloat16 hb = __float2bfloat16(h_reg);
            uint16_t hbits = *(uint16_t*)&hb;
            uint32_t off = (uint32_t)(((1 - p) * NB + bl) * KPADE + jg) * 2;
            st_cluster_b16(rem0 + off, hbits);
            st_cluster_b16(rem1 + off, hbits);
            st_cluster_b16(rem2 + off, hbits);
            st_cluster_b16(rem3 + off, hbits);
            g_feats[((size_t)bglob * TT + t) * (2 * HH) + dir * HH + jg] = h_reg;
        }
        cluster_bar();
        p ^= 1;
    }

    // tail t in [maxlen, TT): fwd -> frozen h, bwd -> zeros
    if (tid < 400) {
        float tv = dir ? 0.f : h_reg;
        for (int t = maxlen; t < TT; t++)
            g_feats[((size_t)bglob * TT + t) * (2 * HH) + dir * HH + jg] = tv;
    }
}

// ---------------- 4. fc + log_softmax (warp per token) ----------------
__global__ void logits_kernel(const float* __restrict__ fcw,
                              const float* __restrict__ fcb) {
    int warp = (blockIdx.x * blockDim.x + threadIdx.x) >> 5;
    int lane = threadIdx.x & 31;
    if (warp >= M_ROWS) return;
    const float4* f4 = (const float4*)(g_feats + (size_t)warp * 400);
    float acc;
    if (lane < CC) {
        const float4* w4 = (const float4*)(fcw + (size_t)lane * 400);
        float a = 0.f;
        #pragma unroll 4
        for (int k = 0; k < 100; k++) {
            float4 f = f4[k], w = w4[k];
            a = fmaf(f.x, w.x, a); a = fmaf(f.y, w.y, a);
            a = fmaf(f.z, w.z, a); a = fmaf(f.w, w.w, a);
        }
        acc = a + fcb[lane];
    } else {
        acc = -INFINITY;
    }
    float m = acc;
    #pragma unroll
    for (int o = 16; o; o >>= 1) m = fmaxf(m, __shfl_xor_sync(~0u, m, o));
    float e = (lane < CC) ? expf(acc - m) : 0.f;
    float ss = e;
    #pragma unroll
    for (int o = 16; o; o >>= 1) ss += __shfl_xor_sync(~0u, ss, o);
    float lse = m + logf(ss);
    if (lane < CC) g_logits[(size_t)warp * CC + lane] = acc - lse;
}

// ---------------- 5. CRF NLL per batch (one warp per sample) ----------------
__global__ void crf_kernel(const int* __restrict__ target,
                           const int* __restrict__ seq_len,
                           const float* __restrict__ trans,
                           const float* __restrict__ start_s,
                           const float* __restrict__ end_s) {
    int b = blockIdx.x;
    int lane = threadIdx.x;          // 32
    __shared__ float s_trans[CC * CC];
    __shared__ float s_alpha[CC];
    for (int i = lane; i < CC * CC; i += 32) s_trans[i] = trans[i];
    int len = seq_len[b];
    const float* lg = g_logits + (size_t)b * TT * CC;
    const int* tg = target + (size_t)b * TT;
    if (lane < CC) s_alpha[lane] = start_s[lane] + lg[lane];
    __syncthreads();

    for (int t = 1; t < TT; t++) {
        if (t >= len) break;
        float newa = 0.f;
        if (lane < CC) {
            float m = -INFINITY;
            #pragma unroll
            for (int i = 0; i < CC; i++)
                m = fmaxf(m, s_alpha[i] + s_trans[i * CC + lane]);
            float s = 0.f;
            #pragma unroll
            for (int i = 0; i < CC; i++)
                s += __expf(s_alpha[i] + s_trans[i * CC + lane] - m);
            newa = m + __logf(s) + lg[t * CC + lane];
        }
        __syncthreads();
        if (lane < CC) s_alpha[lane] = newa;
        __syncthreads();
    }

    float v = (lane < CC) ? s_alpha[lane] + end_s[lane] : -INFINITY;
    float m = v;
    #pragma unroll
    for (int o = 16; o; o >>= 1) m = fmaxf(m, __shfl_xor_sync(~0u, m, o));
    float e = (lane < CC) ? expf(v - m) : 0.f;
    float ss = e;
    #pragma unroll
    for (int o = 16; o; o >>= 1) ss += __shfl_xor_sync(~0u, ss, o);
    float logZ = m + logf(ss);

    float es = 0.f;
    for (int t = lane; t < len; t += 32) es += lg[t * CC + tg[t]];
    float ts = 0.f;
    for (int t = 1 + lane; t < len; t += 32) ts += s_trans[tg[t - 1] * CC + tg[t]];
    float g = es + ts;
    #pragma unroll
    for (int o = 16; o; o >>= 1) g += __shfl_xor_sync(~0u, g, o);
    if (lane == 0) {
        float gold = g + start_s[tg[0]] + end_s[tg[len - 1]];
        g_lossb[b] = logZ - gold;
    }
}

// ---------------- 6. mean reduce ----------------
__global__ void reduce_loss_kernel(float* out) {
    int lane = threadIdx.x;
    float s = g_lossb[lane] + g_lossb[lane + 32];
    #pragma unroll
    for (int o = 16; o; o >>= 1) s += __shfl_xor_sync(~0u, s, o);
    if (lane == 0) out[0] = s * (1.f / BB);
}

// ---------------- launch ----------------
extern "C" void kernel_launch(void* const* d_in, const int* in_sizes, int n_in,
                              void* d_out, int out_size) {
    const int*   words   = (const int*)  d_in[0];
    const int*   seq_len = (const int*)  d_in[1];
    const int*   target  = (const int*)  d_in[2];
    const float* table   = (const float*)d_in[3];
    const float* gamma   = (const float*)d_in[4];
    const float* beta    = (const float*)d_in[5];
    const float* w_ih_f  = (const float*)d_in[6];
    const float* w_hh_f  = (const float*)d_in[7];
    const float* b_f     = (const float*)d_in[8];
    const float* w_ih_b  = (const float*)d_in[9];
    const float* w_hh_b  = (const float*)d_in[10];
    const float* b_b     = (const float*)d_in[11];
    const float* fc_w    = (const float*)d_in[12];
    const float* fc_b    = (const float*)d_in[13];
    const float* trans   = (const float*)d_in[14];
    const float* start_s = (const float*)d_in[15];
    const float* end_s   = (const float*)d_in[16];
    float* out = (float*)d_out;

    cudaFuncSetAttribute(lstm_cluster_kernel,
                         cudaFuncAttributeMaxDynamicSharedMemorySize, LSTM_SMEM);
    cudaFuncSetAttribute(gemm_gates_kernel,
                         cudaFuncAttributeMaxDynamicSharedMemorySize, GEMM_SMEM);

    embed_ln_kernel<<<M_ROWS, 256>>>(words, table, gamma, beta);

    dim3 ggrid((G4 + 63) / 64, M_ROWS / 128, 2);
    gemm_gates_kernel<<<ggrid, 256, GEMM_SMEM>>>(w_ih_f, b_f, w_ih_b, b_b);

    lstm_cluster_kernel<<<16 * NRANK, 512, LSTM_SMEM>>>(seq_len, w_hh_f, w_hh_b);

    logits_kernel<<<M_ROWS / 8, 256>>>(fc_w, fc_b);

    crf_kernel<<<BB, 32>>>(target, seq_len, trans, start_s, end_s);
    reduce_loss_kernel<<<1, 32>>>(out);
}